// round 1
// baseline (speedup 1.0000x reference)
#include <cuda_runtime.h>

#define BB      512
#define INF     512
#define OUTF    64
#define KK      16
#define NN      1024   // OUTF * KK
#define OUTCOLS 576    // INF + OUTF

// Scratch: M = x @ T.reshape(IN, OUT*K), shape (B, 1024), row-major.
__device__ float g_M[BB * NN];

// ---------------------------------------------------------------------------
// GEMM: M[b][n] = sum_in x[b][in] * T[in][n],  (512x512) @ (512x1024)
// 64x64 block tile, 256 threads, 4x4 register micro-tile, k-tile = 16.
// ---------------------------------------------------------------------------
__global__ __launch_bounds__(256) void gemm_kernel(const float* __restrict__ x,
                                                   const float* __restrict__ T) {
    __shared__ float As[16][65];   // A^T tile (padded to kill store conflicts)
    __shared__ float Bs[16][64];

    const int tx = threadIdx.x & 15;   // col group 0..15
    const int ty = threadIdx.x >> 4;   // row group 0..15
    const int rowBase = blockIdx.y * 64;
    const int colBase = blockIdx.x * 64;

    float acc[4][4];
#pragma unroll
    for (int r = 0; r < 4; ++r)
#pragma unroll
        for (int c = 0; c < 4; ++c) acc[r][c] = 0.f;

    for (int k0 = 0; k0 < INF; k0 += 16) {
        // Load A tile: 64 rows x 16 k  (each thread: one float4)
        {
            int r  = threadIdx.x >> 2;        // 0..63
            int kg = (threadIdx.x & 3) * 4;   // 0,4,8,12
            float4 v = *(const float4*)&x[(rowBase + r) * INF + k0 + kg];
            As[kg + 0][r] = v.x;
            As[kg + 1][r] = v.y;
            As[kg + 2][r] = v.z;
            As[kg + 3][r] = v.w;
        }
        // Load B tile: 16 k x 64 cols (each thread: one float4, coalesced)
        {
            int r  = threadIdx.x >> 4;        // 0..15
            int cg = (threadIdx.x & 15) * 4;  // 0..60
            float4 v = *(const float4*)&T[(k0 + r) * NN + colBase + cg];
            *(float4*)&Bs[r][cg] = v;
        }
        __syncthreads();

#pragma unroll
        for (int kk = 0; kk < 16; ++kk) {
            float a[4];
#pragma unroll
            for (int r = 0; r < 4; ++r) a[r] = As[kk][ty * 4 + r];
            float4 b4 = *(const float4*)&Bs[kk][tx * 4];
            float b[4] = {b4.x, b4.y, b4.z, b4.w};
#pragma unroll
            for (int r = 0; r < 4; ++r)
#pragma unroll
                for (int c = 0; c < 4; ++c) acc[r][c] += a[r] * b[c];
        }
        __syncthreads();
    }

#pragma unroll
    for (int r = 0; r < 4; ++r) {
        float4 v = make_float4(acc[r][0], acc[r][1], acc[r][2], acc[r][3]);
        *(float4*)&g_M[(rowBase + ty * 4 + r) * NN + colBase + tx * 4] = v;
    }
}

// ---------------------------------------------------------------------------
// Pairwise: for block (o, ic): load M[:, o, :] (512x16 = 32KB) into smem,
// thread i computes sum_j exp(-sum_k |M[i,o,k]-M[j,o,k]|) - 1.
// ---------------------------------------------------------------------------
__global__ __launch_bounds__(128) void pairwise_kernel(float* __restrict__ out) {
    __shared__ float sM[BB * KK];   // 32 KB

    const int o   = blockIdx.x;
    const int ic  = blockIdx.y;
    const int tid = threadIdx.x;

    // Gather column-o slice: g_M[j*1024 + o*16 + k] -> sM[j*16 + k]
    for (int t = tid; t < BB * 4; t += 128) {
        int j = t >> 2;
        int q = t & 3;
        float4 v = *(const float4*)&g_M[j * NN + o * KK + q * 4];
        *(float4*)&sM[j * KK + q * 4] = v;
    }
    __syncthreads();

    const int i = ic * 128 + tid;
    float mi[16];
#pragma unroll
    for (int k = 0; k < 16; ++k) mi[k] = sM[i * KK + k];

    float acc = 0.f;
#pragma unroll 2
    for (int j = 0; j < BB; ++j) {
        const float4* p = (const float4*)&sM[j * KK];
        float4 a0 = p[0], a1 = p[1], a2 = p[2], a3 = p[3];

        float s0 = (fabsf(mi[0]  - a0.x) + fabsf(mi[1]  - a0.y)) +
                   (fabsf(mi[2]  - a0.z) + fabsf(mi[3]  - a0.w));
        float s1 = (fabsf(mi[4]  - a1.x) + fabsf(mi[5]  - a1.y)) +
                   (fabsf(mi[6]  - a1.z) + fabsf(mi[7]  - a1.w));
        float s2 = (fabsf(mi[8]  - a2.x) + fabsf(mi[9]  - a2.y)) +
                   (fabsf(mi[10] - a2.z) + fabsf(mi[11] - a2.w));
        float s3 = (fabsf(mi[12] - a3.x) + fabsf(mi[13] - a3.y)) +
                   (fabsf(mi[14] - a3.z) + fabsf(mi[15] - a3.w));

        float norm = (s0 + s1) + (s2 + s3);
        acc += __expf(-norm);          // j==i contributes exactly 1.0
    }

    out[i * OUTCOLS + INF + o] = acc - 1.0f;
}

// ---------------------------------------------------------------------------
// Copy x into the first 512 columns of each output row.
// ---------------------------------------------------------------------------
__global__ __launch_bounds__(256) void copy_x_kernel(const float* __restrict__ x,
                                                     float* __restrict__ out) {
    int idx = blockIdx.x * blockDim.x + threadIdx.x;  // over 512*128 float4
    int i = idx >> 7;        // row
    int c = idx & 127;       // float4 index within row
    float4 v = *(const float4*)&x[i * INF + c * 4];
    *(float4*)&out[i * OUTCOLS + c * 4] = v;
}

extern "C" void kernel_launch(void* const* d_in, const int* in_sizes, int n_in,
                              void* d_out, int out_size) {
    const float* x = (const float*)d_in[0];
    const float* T = (const float*)d_in[1];
    float* out = (float*)d_out;

    gemm_kernel<<<dim3(NN / 64, BB / 64), 256>>>(x, T);
    pairwise_kernel<<<dim3(OUTF, 4), 128>>>(out);
    copy_x_kernel<<<(BB * (INF / 4)) / 256, 256>>>(x, out);
}